// round 8
// baseline (speedup 1.0000x reference)
#include <cuda_runtime.h>
#include <cuda_bf16.h>

// Problem constants (fixed by the dataset)
#define NN 100000
#define EE 600000
#define C_IN 128
#define C_HID 128
#define C_OUT 64

// ---------------- scratch (device globals; no allocation allowed) ----------
__device__ __align__(16) float g_dinv[NN];           // degree, then deg^{-1/2}
__device__ __align__(16) int   g_srcs[EE];
__device__ __align__(16) int   g_dsts[EE];
__device__ __align__(16) float g_norm[EE];
__device__ __align__(16) float g_h  [(size_t)NN * C_HID];  // x@W1
__device__ __align__(16) float g_agg[(size_t)NN * C_HID];  // layer-1 aggregate -> hidden
__device__ __align__(16) float g_h2 [(size_t)NN * C_OUT];  // hid@W2
__device__ int g_is64;                               // edge_index dtype flag

// ---------------- dtype detection ------------------------------------------
// int64 indices < 2^17 -> every high 32-bit word is 0.
// int32 indices -> "high words" are random node ids, virtually never all 0.
__global__ void k_detect(const void* __restrict__ ei) {
    if (threadIdx.x == 0 && blockIdx.x == 0) {
        const unsigned long long* p = (const unsigned long long*)ei;
        int is64 = 1;
        for (int i = 0; i < 64; i++) {
            if ((p[i] >> 32) != 0ull) { is64 = 0; break; }
        }
        g_is64 = is64;
    }
}

__device__ __forceinline__ int load_idx(const void* ei, size_t pos, int is64) {
    return is64 ? (int)((const long long*)ei)[pos] : ((const int*)ei)[pos];
}

// ---------------- small prep kernels ---------------------------------------
__global__ void k_deg_init(int n) {
    int i = blockIdx.x * blockDim.x + threadIdx.x;
    if (i < n) g_dinv[i] = 1.0f;   // self-loop contributes 1 to degree
}

__global__ void k_deg_acc(const void* __restrict__ ei, int E) {
    int e = blockIdx.x * blockDim.x + threadIdx.x;
    if (e < E) {
        int d = load_idx(ei, (size_t)E + e, g_is64);
        atomicAdd(&g_dinv[d], 1.0f);
    }
}

__global__ void k_dinv(int n) {
    int i = blockIdx.x * blockDim.x + threadIdx.x;
    if (i < n) g_dinv[i] = rsqrtf(g_dinv[i]);
}

__global__ void k_edge_prep(const void* __restrict__ ei, int E) {
    int e = blockIdx.x * blockDim.x + threadIdx.x;
    if (e < E) {
        int is64 = g_is64;
        int s = load_idx(ei, (size_t)e, is64);
        int d = load_idx(ei, (size_t)E + e, is64);
        g_srcs[e] = s;
        g_dsts[e] = d;
        g_norm[e] = g_dinv[s] * g_dinv[d];
    }
}

__global__ void k_zero_agg(int n4) {
    int t = blockIdx.x * blockDim.x + threadIdx.x;
    if (t < n4) reinterpret_cast<float4*>(g_agg)[t] = make_float4(0.f, 0.f, 0.f, 0.f);
}

// ---------------- SGEMM: C[M,BN] = A[M,128] @ B[128,BN] --------------------
// BM=128, BK=16, TM=8; threads = (BN/TN)*(BM/TM) = 256 for (BN,TN)=(128,8),(64,4)
template <int BN, int TN>
__global__ void k_sgemm(const float* __restrict__ A, const float* __restrict__ B,
                        float* __restrict__ C, int M) {
    constexpr int BM = 128, BK = 16, TM = 8;
    __shared__ float As[BK][BM];
    __shared__ float Bs[BK][BN];

    const int block_row = blockIdx.x * BM;
    const int tx = threadIdx.x % (BN / TN);   // 0..15
    const int ty = threadIdx.x / (BN / TN);   // 0..15

    float acc[TM][TN];
#pragma unroll
    for (int i = 0; i < TM; i++)
#pragma unroll
        for (int j = 0; j < TN; j++) acc[i][j] = 0.f;

    for (int k0 = 0; k0 < 128; k0 += BK) {
        // load A tile (BM x BK), transposed into As[k][m]
#pragma unroll
        for (int j = 0; j < 2; j++) {
            int idx = threadIdx.x * 2 + j;     // 0..511 over [BM][BK/4]
            int r   = idx >> 2;                // 0..127
            int c4  = idx & 3;                 // 0..3
            int grow = block_row + r;
            float4 v = (grow < M)
                ? *reinterpret_cast<const float4*>(A + (size_t)grow * 128 + k0 + c4 * 4)
                : make_float4(0.f, 0.f, 0.f, 0.f);
            As[c4 * 4 + 0][r] = v.x;
            As[c4 * 4 + 1][r] = v.y;
            As[c4 * 4 + 2][r] = v.z;
            As[c4 * 4 + 3][r] = v.w;
        }
        // load B tile (BK x BN)
#pragma unroll
        for (int j = 0; j < BN / 64; j++) {
            int idx = threadIdx.x * (BN / 64) + j;  // over [BK][BN/4]
            int r   = idx / (BN / 4);
            int c4  = idx % (BN / 4);
            float4 v = *reinterpret_cast<const float4*>(B + (size_t)(k0 + r) * BN + c4 * 4);
            *reinterpret_cast<float4*>(&Bs[r][c4 * 4]) = v;
        }
        __syncthreads();

#pragma unroll
        for (int k = 0; k < BK; k++) {
            float ra[TM], rb[TN];
#pragma unroll
            for (int i = 0; i < TM; i++) ra[i] = As[k][ty * TM + i];
#pragma unroll
            for (int j = 0; j < TN; j++) rb[j] = Bs[k][tx * TN + j];
#pragma unroll
            for (int i = 0; i < TM; i++)
#pragma unroll
                for (int j = 0; j < TN; j++) acc[i][j] += ra[i] * rb[j];
        }
        __syncthreads();
    }

#pragma unroll
    for (int i = 0; i < TM; i++) {
        int grow = block_row + ty * TM + i;
        if (grow < M) {
#pragma unroll
            for (int j = 0; j < TN; j += 4) {
                float4 v = make_float4(acc[i][j], acc[i][j + 1], acc[i][j + 2], acc[i][j + 3]);
                *reinterpret_cast<float4*>(C + (size_t)grow * BN + tx * TN + j) = v;
            }
        }
    }
}

// ---------------- edge scatter: agg[dst] += norm * h[src] ------------------
// one thread per float4 chunk of an edge; 4 scalar no-return atomicAdds
// (nvcc lowers unused-return atomicAdd to RED.E.ADD.F32)
template <int C>
__global__ void k_scatter(const float* __restrict__ h, float* __restrict__ agg, int E) {
    constexpr int C4 = C / 4;
    int t = blockIdx.x * blockDim.x + threadIdx.x;
    int e = t / C4;
    if (e >= E) return;
    int c = (t % C4) * 4;
    int s = g_srcs[e];
    int d = g_dsts[e];
    float w = g_norm[e];
    float4 hv = *reinterpret_cast<const float4*>(h + (size_t)s * C + c);
    float* p = agg + (size_t)d * C + c;
    atomicAdd(p + 0, hv.x * w);
    atomicAdd(p + 1, hv.y * w);
    atomicAdd(p + 2, hv.z * w);
    atomicAdd(p + 3, hv.w * w);
}

// ---------------- epilogue: agg = [prelu](agg + dinv^2*h + b) --------------
template <int C, bool PRELU>
__global__ void k_epilogue(const float* __restrict__ h, const float* __restrict__ bias,
                           float* __restrict__ agg, const float* __restrict__ prelu_a,
                           int n) {
    constexpr int C4 = C / 4;
    int t = blockIdx.x * blockDim.x + threadIdx.x;
    int i = t / C4;
    if (i >= n) return;
    int c = (t % C4) * 4;
    float di = g_dinv[i];
    float w = di * di;
    float4 hv = *reinterpret_cast<const float4*>(h + (size_t)i * C + c);
    float4 av = *reinterpret_cast<const float4*>(agg + (size_t)i * C + c);
    float4 bv = *reinterpret_cast<const float4*>(bias + c);
    float vx = av.x + w * hv.x + bv.x;
    float vy = av.y + w * hv.y + bv.y;
    float vz = av.z + w * hv.z + bv.z;
    float vw = av.w + w * hv.w + bv.w;
    if constexpr (PRELU) {
        float a = prelu_a[0];
        vx = vx >= 0.f ? vx : a * vx;
        vy = vy >= 0.f ? vy : a * vy;
        vz = vz >= 0.f ? vz : a * vz;
        vw = vw >= 0.f ? vw : a * vw;
    }
    *reinterpret_cast<float4*>(agg + (size_t)i * C + c) = make_float4(vx, vy, vz, vw);
}

// ---------------- launch ----------------------------------------------------
extern "C" void kernel_launch(void* const* d_in, const int* in_sizes, int n_in,
                              void* d_out, int out_size) {
    const float* x   = (const float*)d_in[0];
    const void*  ei  = d_in[1];              // int32 or int64, auto-detected
    const float* W1  = (const float*)d_in[2];
    const float* b1  = (const float*)d_in[3];
    const float* W2  = (const float*)d_in[4];
    const float* b2  = (const float*)d_in[5];
    const float* pa  = (const float*)d_in[6];
    float*       out = (float*)d_out;

    const int N = in_sizes[0] / C_IN;   // 100000
    const int E = in_sizes[1] / 2;      // 600000

    void *p_h_v, *p_agg_v, *p_h2_v;
    cudaGetSymbolAddress(&p_h_v, g_h);
    cudaGetSymbolAddress(&p_agg_v, g_agg);
    cudaGetSymbolAddress(&p_h2_v, g_h2);
    float* p_h   = (float*)p_h_v;
    float* p_agg = (float*)p_agg_v;
    float* p_h2  = (float*)p_h2_v;

    const int NT = 256;
    // zero accumulators
    cudaMemsetAsync(d_out, 0, (size_t)out_size * sizeof(float));
    {
        int n4 = N * (C_HID / 4);
        k_zero_agg<<<(n4 + NT - 1) / NT, NT>>>(n4);
    }

    // dtype detection + degrees + norms
    k_detect<<<1, 32>>>(ei);
    k_deg_init<<<(N + NT - 1) / NT, NT>>>(N);
    k_deg_acc<<<(E + NT - 1) / NT, NT>>>(ei, E);
    k_dinv<<<(N + NT - 1) / NT, NT>>>(N);
    k_edge_prep<<<(E + NT - 1) / NT, NT>>>(ei, E);

    // layer 1: h = x @ W1 ; agg = scatter ; hid = prelu(agg + dinv^2*h + b1)
    k_sgemm<128, 8><<<(N + 127) / 128, 256>>>(x, W1, p_h, N);
    {
        int tot = E * (C_HID / 4);
        k_scatter<C_HID><<<(tot + NT - 1) / NT, NT>>>(p_h, p_agg, E);
    }
    {
        int tot = N * (C_HID / 4);
        k_epilogue<C_HID, true><<<(tot + NT - 1) / NT, NT>>>(p_h, b1, p_agg, pa, N);
    }

    // layer 2: h2 = hid @ W2 ; out = scatter + dinv^2*h2 + b2
    k_sgemm<64, 4><<<(N + 127) / 128, 256>>>(p_agg, W2, p_h2, N);
    {
        int tot = E * (C_OUT / 4);
        k_scatter<C_OUT><<<(tot + NT - 1) / NT, NT>>>(p_h2, out, E);
    }
    {
        int tot = N * (C_OUT / 4);
        k_epilogue<C_OUT, false><<<(tot + NT - 1) / NT, NT>>>(p_h2, b2, out, nullptr, N);
    }
}

// round 9
// speedup vs baseline: 1.9174x; 1.9174x over previous
#include <cuda_runtime.h>
#include <cuda_bf16.h>

// Problem constants (fixed by the dataset)
#define NN 100000
#define EE 600000
#define C_IN 128
#define C_HID 128
#define C_OUT 64

#define SCAN_T 512
#define NB_MAX 256   // ceil(NN/SCAN_T) = 196 <= 256

// ---------------- scratch (device globals; no allocation allowed) ----------
__device__ __align__(16) int   g_cnt[NN];            // in-degree (edges only)
__device__ __align__(16) float g_dinv[NN];           // deg^{-1/2}
__device__ __align__(16) int   g_rowptr[NN + 1];
__device__ __align__(16) int   g_fill[NN];
__device__ __align__(16) int   g_bsum[NB_MAX];
__device__ __align__(16) int   g_bsumex[NB_MAX];
__device__ __align__(16) int   g_csr_src[EE];
__device__ __align__(16) float g_csr_w[EE];
__device__ __align__(16) float g_h  [(size_t)NN * C_HID];  // x@W1
__device__ __align__(16) float g_agg[(size_t)NN * C_HID];  // hidden (post-prelu)
__device__ __align__(16) float g_h2 [(size_t)NN * C_OUT];  // hid@W2
__device__ int g_is64;                               // edge_index dtype flag

// ---------------- dtype detection ------------------------------------------
// int64 indices < 2^17 -> every high 32-bit word is 0.
// int32 indices -> "high words" are random node ids, virtually never all 0.
__global__ void k_detect(const void* __restrict__ ei) {
    if (threadIdx.x == 0 && blockIdx.x == 0) {
        const unsigned long long* p = (const unsigned long long*)ei;
        int is64 = 1;
        for (int i = 0; i < 64; i++) {
            if ((p[i] >> 32) != 0ull) { is64 = 0; break; }
        }
        g_is64 = is64;
    }
}

__device__ __forceinline__ int load_idx(const void* ei, size_t pos, int is64) {
    return is64 ? (int)((const long long*)ei)[pos] : ((const int*)ei)[pos];
}

// ---------------- degree histogram + dinv -----------------------------------
__global__ void k_hist(const void* __restrict__ ei, int E) {
    int e = blockIdx.x * blockDim.x + threadIdx.x;
    if (e < E) {
        int d = load_idx(ei, (size_t)E + e, g_is64);
        atomicAdd(&g_cnt[d], 1);
    }
}

__global__ void k_dinv(int n) {
    int i = blockIdx.x * blockDim.x + threadIdx.x;
    if (i < n) g_dinv[i] = rsqrtf((float)g_cnt[i] + 1.0f);  // +1: self-loop
}

// ---------------- exclusive scan of g_cnt -> g_rowptr ------------------------
__global__ void k_scan1(int n) {
    __shared__ int sm[2][SCAN_T];
    int t = threadIdx.x, b = blockIdx.x;
    int i = b * SCAN_T + t;
    int v = (i < n) ? g_cnt[i] : 0;
    int pi = 0;
    sm[0][t] = v;
    __syncthreads();
#pragma unroll
    for (int off = 1; off < SCAN_T; off <<= 1) {
        int po = pi ^ 1;
        sm[po][t] = (t >= off) ? sm[pi][t] + sm[pi][t - off] : sm[pi][t];
        pi = po;
        __syncthreads();
    }
    int inc = sm[pi][t];
    if (i < n) g_rowptr[i] = inc - v;          // block-local exclusive
    if (t == SCAN_T - 1) g_bsum[b] = inc;      // block total
}

__global__ void k_scan2(int nb) {
    __shared__ int sm[2][NB_MAX];
    int t = threadIdx.x;
    int v = (t < nb) ? g_bsum[t] : 0;
    int pi = 0;
    sm[0][t] = v;
    __syncthreads();
#pragma unroll
    for (int off = 1; off < NB_MAX; off <<= 1) {
        int po = pi ^ 1;
        sm[po][t] = (t >= off) ? sm[pi][t] + sm[pi][t - off] : sm[pi][t];
        pi = po;
        __syncthreads();
    }
    g_bsumex[t] = sm[pi][t] - v;               // exclusive block offsets
}

__global__ void k_scan3(int n, int E) {
    int i = blockIdx.x * blockDim.x + threadIdx.x;
    if (i < n) g_rowptr[i] += g_bsumex[i / SCAN_T];
    if (i == 0) g_rowptr[n] = E;
}

// ---------------- CSR fill ---------------------------------------------------
__global__ void k_fill(const void* __restrict__ ei, int E) {
    int e = blockIdx.x * blockDim.x + threadIdx.x;
    if (e < E) {
        int is64 = g_is64;
        int s = load_idx(ei, (size_t)e, is64);
        int d = load_idx(ei, (size_t)E + e, is64);
        int pos = g_rowptr[d] + atomicAdd(&g_fill[d], 1);
        g_csr_src[pos] = s;
        g_csr_w[pos] = g_dinv[s] * g_dinv[d];
    }
}

// ---------------- SGEMM with packed fma.rn.f32x2 ----------------------------
// C[M,BN] = A[M,128] @ B[128,BN]; BM=128, BK=16, TM=8; 256 threads.
template <int BN, int TN>
__global__ void k_sgemm(const float* __restrict__ A, const float* __restrict__ B,
                        float* __restrict__ C, int M) {
    constexpr int BM = 128, BK = 16, TM = 8, TN2 = TN / 2;
    __shared__ float As[BK][BM];
    __shared__ float Bs[BK][BN];

    const int block_row = blockIdx.x * BM;
    const int tx = threadIdx.x % (BN / TN);   // 0..15
    const int ty = threadIdx.x / (BN / TN);   // 0..15

    unsigned long long acc[TM][TN2] = {};     // f32x2 pairs, zero-init

    for (int k0 = 0; k0 < 128; k0 += BK) {
        // load A tile (BM x BK), transposed into As[k][m]
#pragma unroll
        for (int j = 0; j < 2; j++) {
            int idx = threadIdx.x * 2 + j;     // 0..511 over [BM][BK/4]
            int r   = idx >> 2;
            int c4  = idx & 3;
            int grow = block_row + r;
            float4 v = (grow < M)
                ? *reinterpret_cast<const float4*>(A + (size_t)grow * 128 + k0 + c4 * 4)
                : make_float4(0.f, 0.f, 0.f, 0.f);
            As[c4 * 4 + 0][r] = v.x;
            As[c4 * 4 + 1][r] = v.y;
            As[c4 * 4 + 2][r] = v.z;
            As[c4 * 4 + 3][r] = v.w;
        }
        // load B tile (BK x BN)
#pragma unroll
        for (int j = 0; j < BN / 64; j++) {
            int idx = threadIdx.x * (BN / 64) + j;
            int r   = idx / (BN / 4);
            int c4  = idx % (BN / 4);
            float4 v = *reinterpret_cast<const float4*>(B + (size_t)(k0 + r) * BN + c4 * 4);
            *reinterpret_cast<float4*>(&Bs[r][c4 * 4]) = v;
        }
        __syncthreads();

#pragma unroll
        for (int k = 0; k < BK; k++) {
            unsigned long long rap[TM];
#pragma unroll
            for (int i = 0; i < TM; i++) {
                unsigned r = __float_as_uint(As[k][ty * TM + i]);
                asm("mov.b64 %0, {%1, %1};" : "=l"(rap[i]) : "r"(r));
            }
            const unsigned long long* brow =
                reinterpret_cast<const unsigned long long*>(&Bs[k][tx * TN]);
            unsigned long long rbp[TN2];
#pragma unroll
            for (int j = 0; j < TN2; j++) rbp[j] = brow[j];
#pragma unroll
            for (int i = 0; i < TM; i++)
#pragma unroll
                for (int j = 0; j < TN2; j++)
                    asm("fma.rn.f32x2 %0, %1, %2, %0;"
                        : "+l"(acc[i][j]) : "l"(rap[i]), "l"(rbp[j]));
        }
        __syncthreads();
    }

#pragma unroll
    for (int i = 0; i < TM; i++) {
        int grow = block_row + ty * TM + i;
        if (grow < M) {
#pragma unroll
            for (int j = 0; j < TN2; j += 2) {
                unsigned a0, a1, b0, b1;
                asm("mov.b64 {%0, %1}, %2;" : "=r"(a0), "=r"(a1) : "l"(acc[i][j]));
                asm("mov.b64 {%0, %1}, %2;" : "=r"(b0), "=r"(b1) : "l"(acc[i][j + 1]));
                float4 v = make_float4(__uint_as_float(a0), __uint_as_float(a1),
                                       __uint_as_float(b0), __uint_as_float(b1));
                *reinterpret_cast<float4*>(C + (size_t)grow * BN + tx * TN + j * 2) = v;
            }
        }
    }
}

// ---------------- CSR aggregation, C=128: one warp per node ------------------
// out[i] = prelu( sum_e w_e * h[src_e] + dinv[i]^2 * h[i] + bias )
__global__ void k_agg128(const float* __restrict__ h, const float* __restrict__ bias,
                         const float* __restrict__ prelu_a, float* __restrict__ o, int N) {
    int gt = blockIdx.x * blockDim.x + threadIdx.x;
    int i = gt >> 5, lane = gt & 31;
    if (i >= N) return;
    const float4* __restrict__ H = (const float4*)h;
    int e   = g_rowptr[i];
    int end = g_rowptr[i + 1];
    float4 acc = make_float4(0.f, 0.f, 0.f, 0.f);
    // 2-way unrolled edge loop for MLP
    for (; e + 1 < end; e += 2) {
        int   s0 = __ldg(&g_csr_src[e]),     s1 = __ldg(&g_csr_src[e + 1]);
        float w0 = __ldg(&g_csr_w[e]),       w1 = __ldg(&g_csr_w[e + 1]);
        float4 v0 = H[(size_t)s0 * 32 + lane];
        float4 v1 = H[(size_t)s1 * 32 + lane];
        acc.x = fmaf(w0, v0.x, acc.x); acc.y = fmaf(w0, v0.y, acc.y);
        acc.z = fmaf(w0, v0.z, acc.z); acc.w = fmaf(w0, v0.w, acc.w);
        acc.x = fmaf(w1, v1.x, acc.x); acc.y = fmaf(w1, v1.y, acc.y);
        acc.z = fmaf(w1, v1.z, acc.z); acc.w = fmaf(w1, v1.w, acc.w);
    }
    if (e < end) {
        int   s0 = __ldg(&g_csr_src[e]);
        float w0 = __ldg(&g_csr_w[e]);
        float4 v0 = H[(size_t)s0 * 32 + lane];
        acc.x = fmaf(w0, v0.x, acc.x); acc.y = fmaf(w0, v0.y, acc.y);
        acc.z = fmaf(w0, v0.z, acc.z); acc.w = fmaf(w0, v0.w, acc.w);
    }
    float di = g_dinv[i], ws = di * di;
    float4 sv = H[(size_t)i * 32 + lane];
    float4 bv = ((const float4*)bias)[lane];
    float r0 = fmaf(ws, sv.x, acc.x) + bv.x;
    float r1 = fmaf(ws, sv.y, acc.y) + bv.y;
    float r2 = fmaf(ws, sv.z, acc.z) + bv.z;
    float r3 = fmaf(ws, sv.w, acc.w) + bv.w;
    float a = prelu_a[0];
    r0 = r0 >= 0.f ? r0 : a * r0;
    r1 = r1 >= 0.f ? r1 : a * r1;
    r2 = r2 >= 0.f ? r2 : a * r2;
    r3 = r3 >= 0.f ? r3 : a * r3;
    ((float4*)o)[(size_t)i * 32 + lane] = make_float4(r0, r1, r2, r3);
}

// ---------------- CSR aggregation, C=64: 16 threads per node -----------------
__global__ void k_agg64(const float* __restrict__ h, const float* __restrict__ bias,
                        float* __restrict__ o, int N) {
    int gt = blockIdx.x * blockDim.x + threadIdx.x;
    int i = gt >> 4, l = gt & 15;
    if (i >= N) return;
    const float4* __restrict__ H = (const float4*)h;
    int e   = g_rowptr[i];
    int end = g_rowptr[i + 1];
    float4 acc = make_float4(0.f, 0.f, 0.f, 0.f);
    for (; e + 1 < end; e += 2) {
        int   s0 = __ldg(&g_csr_src[e]),     s1 = __ldg(&g_csr_src[e + 1]);
        float w0 = __ldg(&g_csr_w[e]),       w1 = __ldg(&g_csr_w[e + 1]);
        float4 v0 = H[(size_t)s0 * 16 + l];
        float4 v1 = H[(size_t)s1 * 16 + l];
        acc.x = fmaf(w0, v0.x, acc.x); acc.y = fmaf(w0, v0.y, acc.y);
        acc.z = fmaf(w0, v0.z, acc.z); acc.w = fmaf(w0, v0.w, acc.w);
        acc.x = fmaf(w1, v1.x, acc.x); acc.y = fmaf(w1, v1.y, acc.y);
        acc.z = fmaf(w1, v1.z, acc.z); acc.w = fmaf(w1, v1.w, acc.w);
    }
    if (e < end) {
        int   s0 = __ldg(&g_csr_src[e]);
        float w0 = __ldg(&g_csr_w[e]);
        float4 v0 = H[(size_t)s0 * 16 + l];
        acc.x = fmaf(w0, v0.x, acc.x); acc.y = fmaf(w0, v0.y, acc.y);
        acc.z = fmaf(w0, v0.z, acc.z); acc.w = fmaf(w0, v0.w, acc.w);
    }
    float di = g_dinv[i], ws = di * di;
    float4 sv = H[(size_t)i * 16 + l];
    float4 bv = ((const float4*)bias)[l];
    ((float4*)o)[(size_t)i * 16 + l] = make_float4(
        fmaf(ws, sv.x, acc.x) + bv.x,
        fmaf(ws, sv.y, acc.y) + bv.y,
        fmaf(ws, sv.z, acc.z) + bv.z,
        fmaf(ws, sv.w, acc.w) + bv.w);
}

// ---------------- launch ----------------------------------------------------
extern "C" void kernel_launch(void* const* d_in, const int* in_sizes, int n_in,
                              void* d_out, int out_size) {
    const float* x   = (const float*)d_in[0];
    const void*  ei  = d_in[1];              // int32 or int64, auto-detected
    const float* W1  = (const float*)d_in[2];
    const float* b1  = (const float*)d_in[3];
    const float* W2  = (const float*)d_in[4];
    const float* b2  = (const float*)d_in[5];
    const float* pa  = (const float*)d_in[6];
    float*       out = (float*)d_out;

    const int N = in_sizes[0] / C_IN;   // 100000
    const int E = in_sizes[1] / 2;      // 600000

    void *p_h_v, *p_agg_v, *p_h2_v, *p_cnt_v, *p_fill_v;
    cudaGetSymbolAddress(&p_h_v, g_h);
    cudaGetSymbolAddress(&p_agg_v, g_agg);
    cudaGetSymbolAddress(&p_h2_v, g_h2);
    cudaGetSymbolAddress(&p_cnt_v, g_cnt);
    cudaGetSymbolAddress(&p_fill_v, g_fill);
    float* p_h   = (float*)p_h_v;
    float* p_agg = (float*)p_agg_v;
    float* p_h2  = (float*)p_h2_v;

    const int NT = 256;
    const int nb = (N + SCAN_T - 1) / SCAN_T;   // 196

    // zero counters
    cudaMemsetAsync(p_cnt_v, 0, (size_t)N * sizeof(int));
    cudaMemsetAsync(p_fill_v, 0, (size_t)N * sizeof(int));

    // dtype + degrees + CSR
    k_detect<<<1, 32>>>(ei);
    k_hist<<<(E + NT - 1) / NT, NT>>>(ei, E);
    k_dinv<<<(N + NT - 1) / NT, NT>>>(N);
    k_scan1<<<nb, SCAN_T>>>(N);
    k_scan2<<<1, NB_MAX>>>(nb);
    k_scan3<<<(N + NT - 1) / NT, NT>>>(N, E);
    k_fill<<<(E + NT - 1) / NT, NT>>>(ei, E);

    // layer 1: h = x @ W1 ; hidden = prelu(agg_csr(h) + dinv^2*h + b1)
    k_sgemm<128, 8><<<(N + 127) / 128, 256>>>(x, W1, p_h, N);
    k_agg128<<<(N * 32 + NT - 1) / NT, NT>>>(p_h, b1, pa, p_agg, N);

    // layer 2: h2 = hidden @ W2 ; out = agg_csr(h2) + dinv^2*h2 + b2
    k_sgemm<64, 4><<<(N + 127) / 128, 256>>>(p_agg, W2, p_h2, N);
    k_agg64<<<(N * 16 + NT - 1) / NT, NT>>>(p_h2, b2, out, N);
}